// round 17
// baseline (speedup 1.0000x reference)
#include <cuda_runtime.h>
#include <cuda_fp16.h>
#include <cstdint>

// ============================================================================
// DIN scorer R16: tail weights re-packed to k-quad float4 (fp32, bit-exact,
// 4x fewer LDG instructions in the latency-bound tail). din/cvec unchanged.
// ============================================================================

#define BB 2048
#define LL 200

__device__ float g_attn[BB * 128];
__device__ float g_cvec[BB * 128];
// fp32 k-quad packed weights: g_Wq[kq*N + j] = (W[4kq][j],...,W[4kq+3][j])
__device__ float4 g_nwq [32 * 128];
__device__ float4 g_dw1q[96 * 512];
__device__ float4 g_dw2q[128 * 256];
__device__ float4 g_dw3q[64 * 128];

__device__ __forceinline__ float sigm_fast(float x) {
    float y;
    asm("tanh.approx.f32 %0, %1;" : "=f"(y) : "f"(0.5f * x));
    return fmaf(0.5f, y, 0.5f);
}
__device__ __forceinline__ float sigm(float x) {
    return __fdividef(1.0f, 1.0f + __expf(-x));
}

__device__ __forceinline__ uint32_t pack2h(float a, float b) {
    return ((uint32_t)__half_as_ushort(__float2half_rn(b)) << 16)
         |  (uint32_t)__half_as_ushort(__float2half_rn(a));
}

__device__ __forceinline__ void mma_f16(float* c, uint32_t a0, uint32_t a1,
                                        uint32_t a2, uint32_t a3,
                                        uint32_t b0, uint32_t b1) {
    asm("mma.sync.aligned.m16n8k16.row.col.f32.f16.f16.f32 "
        "{%0,%1,%2,%3}, {%4,%5,%6,%7}, {%8,%9}, {%0,%1,%2,%3};"
        : "+f"(c[0]), "+f"(c[1]), "+f"(c[2]), "+f"(c[3])
        : "r"(a0), "r"(a1), "r"(a2), "r"(a3), "r"(b0), "r"(b1));
}

__device__ __forceinline__ void ldsm_x4(uint32_t& r0, uint32_t& r1,
                                        uint32_t& r2, uint32_t& r3,
                                        uint32_t saddr) {
    asm volatile("ldmatrix.sync.aligned.m8n8.x4.shared.b16 {%0,%1,%2,%3}, [%4];"
        : "=r"(r0), "=r"(r1), "=r"(r2), "=r"(r3) : "r"(saddr));
}

__device__ __forceinline__ int pidx(int row, int pair) {
    return row * 64 + (pair ^ ((row & 7) << 2));
}

// ============================================================================
// prep_weights: pack nw/dw1/dw2/dw3 into fp32 k-quad float4 (bit-exact).
// ============================================================================
__global__ __launch_bounds__(512)
void prep_weights(const float* __restrict__ nw,  const float* __restrict__ dw1,
                  const float* __restrict__ dw2, const float* __restrict__ dw3)
{
    const int tid = blockIdx.x * blockDim.x + threadIdx.x;
    const int str = gridDim.x * blockDim.x;
    for (int i = tid; i < 96 * 512; i += str) {
        int kq = i >> 9, j = i & 511;
        g_dw1q[i] = make_float4(dw1[(4 * kq + 0) * 512 + j], dw1[(4 * kq + 1) * 512 + j],
                                dw1[(4 * kq + 2) * 512 + j], dw1[(4 * kq + 3) * 512 + j]);
    }
    for (int i = tid; i < 128 * 256; i += str) {
        int kq = i >> 8, j = i & 255;
        g_dw2q[i] = make_float4(dw2[(4 * kq + 0) * 256 + j], dw2[(4 * kq + 1) * 256 + j],
                                dw2[(4 * kq + 2) * 256 + j], dw2[(4 * kq + 3) * 256 + j]);
    }
    for (int i = tid; i < 64 * 128; i += str) {
        int kq = i >> 7, j = i & 127;
        g_dw3q[i] = make_float4(dw3[(4 * kq + 0) * 128 + j], dw3[(4 * kq + 1) * 128 + j],
                                dw3[(4 * kq + 2) * 128 + j], dw3[(4 * kq + 3) * 128 + j]);
    }
    for (int i = tid; i < 32 * 128; i += str) {
        int kq = i >> 7, j = i & 127;
        g_nwq[i]  = make_float4(nw[(4 * kq + 0) * 128 + j], nw[(4 * kq + 1) * 128 + j],
                                nw[(4 * kq + 2) * 128 + j], nw[(4 * kq + 3) * 128 + j]);
    }
}

// ============================================================================
// cvec_kernel: unchanged (9.5us)
// ============================================================================
__global__ __launch_bounds__(512, 2)
void cvec_kernel(const int*   __restrict__ item_id,
                 const float* __restrict__ item_emb,
                 const float* __restrict__ aw1,
                 const float* __restrict__ ab1)
{
    __shared__ float tT[128 * 8];
    __shared__ float part[4 * 8 * 128];
    const int b0  = blockIdx.x * 8;
    const int tid = threadIdx.x;

    for (int e = tid; e < 128 * 8; e += 512) {
        int k = e >> 3, bb = e & 7;
        long id = (long)__ldg(&item_id[b0 + bb]);
        tT[e] = __ldg(&item_emb[id * 128 + k]);
    }
    __syncthreads();

    const int j  = tid & 127;
    const int kq = tid >> 7;
    float acc[8];
    #pragma unroll
    for (int r = 0; r < 8; ++r) acc[r] = 0.0f;

    #pragma unroll 8
    for (int kk = 0; kk < 32; ++kk) {
        int k = kq * 32 + kk;
        float w = __ldg(&aw1[k * 128 + j]) + __ldg(&aw1[(256 + k) * 128 + j]);
        const float4* tp = reinterpret_cast<const float4*>(tT + k * 8);
        float4 t0 = tp[0], t1 = tp[1];
        acc[0] += t0.x * w; acc[1] += t0.y * w;
        acc[2] += t0.z * w; acc[3] += t0.w * w;
        acc[4] += t1.x * w; acc[5] += t1.y * w;
        acc[6] += t1.z * w; acc[7] += t1.w * w;
    }
    #pragma unroll
    for (int r = 0; r < 8; ++r)
        part[(kq * 8 + r) * 128 + j] = acc[r];
    __syncthreads();

    for (int e = tid; e < 8 * 128; e += 512) {
        int bb = e >> 7, jj = e & 127;
        float s = part[(0 * 8 + bb) * 128 + jj] + part[(1 * 8 + bb) * 128 + jj]
                + part[(2 * 8 + bb) * 128 + jj] + part[(3 * 8 + bb) * 128 + jj]
                + __ldg(&ab1[jj]);
        g_cvec[(b0 + bb) * 128 + jj] = s;
    }
}

// ---- smem byte offsets (din) — 105KB, 2 CTAs/SM ----
#define OFF_SA0     0
#define OFF_SA1     32768
#define OFF_B1      53248
#define OFF_B2      86016
#define OFF_T       102400
#define OFF_CVEC    102912
#define OFF_SCORE   103424
#define OFF_AB2     103936
#define OFF_AFW     104192
#define OFF_RED     104448
#define SMEM_BYTES  104960

template<int CR>
__device__ __forceinline__ void gather_chunk(char* smem, int offHI,
                                             const int* __restrict__ ids,
                                             const float* __restrict__ item_emb,
                                             int tid)
{
    uint32_t* dHI = (uint32_t*)(smem + offHI);
    constexpr int NIT = CR * 32 / 256;
    int idv[NIT];
    #pragma unroll
    for (int i = 0; i < NIT; ++i)
        idv[i] = __ldg(&ids[(tid + i * 256) >> 5]);
    #pragma unroll
    for (int i = 0; i < NIT; ++i) {
        int e = tid + i * 256, row = e >> 5, q = e & 31;
        float4 v = __ldg(reinterpret_cast<const float4*>(item_emb + (long)idv[i] * 128) + q);
        int a = pidx(row, q * 2);
        *(uint2*)(dHI + a) = make_uint2(pack2h(v.x, v.y), pack2h(v.z, v.w));
    }
}

template<int CR>
__device__ __forceinline__ void compute_chunk(char* smem, int offHI,
                                              const int* __restrict__ ids,
                                              float afb0, float& attnReg,
                                              int tid, int wid, int g, int tg,
                                              int rA, int dAt, int half)
{
    uint32_t* saHI = (uint32_t*)(smem + offHI);
    float* cvec   = (float*)(smem + OFF_CVEC);
    float* scoreS = (float*)(smem + OFF_SCORE);
    float* ab2S   = (float*)(smem + OFF_AB2);
    float* afwS   = (float*)(smem + OFF_AFW);

    const int lid = tid & 31;
    const uint32_t saSH = (uint32_t)__cvta_generic_to_shared(saHI);
    const uint32_t b1SH = (uint32_t)__cvta_generic_to_shared(smem + OFF_B1);
    const uint32_t b2SH = (uint32_t)__cvta_generic_to_shared(smem + OFF_B2);

    const int n_local = lid & 7;
    const int mtx     = lid >> 3;
    const int rowA    = wid * 16 + 8 * (mtx & 1) + n_local;
    const int khA     = mtx >> 1;
    const int ntoff   = mtx >> 1;
    const int khB     = mtx & 1;

    const bool act = (wid * 16 < CR);

    uint32_t hT[16], hB[16];

    if (act) {
        float acc[16][4];
        #pragma unroll
        for (int nt = 0; nt < 16; ++nt)
            #pragma unroll
            for (int i = 0; i < 4; ++i) acc[nt][i] = 0.0f;

        #pragma unroll
        for (int ks = 0; ks < 8; ++ks) {
            uint32_t a0, a1, a2, a3;
            ldsm_x4(a0, a1, a2, a3,
                    saSH + 4u * (uint32_t)pidx(rowA, 8 * ks + 4 * khA));
            #pragma unroll
            for (int nt2 = 0; nt2 < 8; ++nt2) {
                const int nt = 2 * nt2;
                const int rowB = 8 * (nt + ntoff) + n_local;
                uint32_t b0, b1, b2, b3;
                ldsm_x4(b0, b1, b2, b3,
                        b1SH + 4u * (uint32_t)pidx(rowB, 8 * ks + 4 * khB));
                mma_f16(acc[nt],     a0, a1, a2, a3, b0, b1);
                mma_f16(acc[nt + 1], a0, a1, a2, a3, b2, b3);
            }
        }
        #pragma unroll
        for (int nt = 0; nt < 16; ++nt) {
            const int c0 = 8 * nt + 2 * tg;
            float t0 = sigm_fast(acc[nt][0] + cvec[c0]);
            float t1 = sigm_fast(acc[nt][1] + cvec[c0 + 1]);
            float b0 = sigm_fast(acc[nt][2] + cvec[c0]);
            float b1 = sigm_fast(acc[nt][3] + cvec[c0 + 1]);
            hT[nt] = pack2h(t0, t1);
            hB[nt] = pack2h(b0, b1);
        }
    }

    float acc2[8][4];
    #pragma unroll
    for (int nt = 0; nt < 8; ++nt)
        #pragma unroll
        for (int i = 0; i < 4; ++i) acc2[nt][i] = 0.0f;

    if (act) {
        #pragma unroll
        for (int ks = 0; ks < 8; ++ks) {
            uint32_t ah0 = hT[2 * ks],     ah1 = hB[2 * ks];
            uint32_t ah2 = hT[2 * ks + 1], ah3 = hB[2 * ks + 1];
            #pragma unroll
            for (int nt2 = 0; nt2 < 4; ++nt2) {
                const int nt = 2 * nt2;
                const int rowB = 8 * (nt + ntoff) + n_local;
                uint32_t b0, b1, b2, b3;
                ldsm_x4(b0, b1, b2, b3,
                        b2SH + 4u * (uint32_t)pidx(rowB, 8 * ks + 4 * khB));
                mma_f16(acc2[nt],     ah0, ah1, ah2, ah3, b0, b1);
                mma_f16(acc2[nt + 1], ah0, ah1, ah2, ah3, b2, b3);
            }
        }
    }

    {
        float vT = 0.0f, vB = 0.0f;
        #pragma unroll
        for (int nt = 0; nt < 8; ++nt) {
            const int c0 = 8 * nt + 2 * tg;
            vT += sigm_fast(acc2[nt][0] + ab2S[c0])     * afwS[c0];
            vT += sigm_fast(acc2[nt][1] + ab2S[c0 + 1]) * afwS[c0 + 1];
            vB += sigm_fast(acc2[nt][2] + ab2S[c0])     * afwS[c0];
            vB += sigm_fast(acc2[nt][3] + ab2S[c0 + 1]) * afwS[c0 + 1];
        }
        vT += __shfl_xor_sync(0xffffffffu, vT, 1);
        vT += __shfl_xor_sync(0xffffffffu, vT, 2);
        vB += __shfl_xor_sync(0xffffffffu, vB, 1);
        vB += __shfl_xor_sync(0xffffffffu, vB, 2);
        if (tg == 0) {
            int r0 = rA, r1 = rA + 8;
            float s0 = 0.0f, s1 = 0.0f;
            if (act && r0 < CR) {
                int id = __ldg(&ids[r0]);
                s0 = (id == 0) ? 0.0f : (vT + afb0);
            }
            if (act && r1 < CR) {
                int id = __ldg(&ids[r1]);
                s1 = (id == 0) ? 0.0f : (vB + afb0);
            }
            scoreS[r0] = s0;
            if (r1 < 128) scoreS[r1] = s1;
        }
    }
    __syncthreads();

    {
        const int h0 = half * (CR >> 1);
        const int h1 = h0 + (CR >> 1);
        const int pr = dAt >> 1, sel = (dAt & 1) * 16;
        for (int row = h0; row < h1; ++row) {
            float sc = scoreS[row];
            uint32_t whi = saHI[pidx(row, pr)];
            float s = __half2float(__ushort_as_half((unsigned short)(whi >> sel)));
            attnReg += sc * s;
        }
    }
    __syncthreads();
}

__global__ __launch_bounds__(256, 2)
void din_attention_mma(const int*   __restrict__ in_item_id,
                       const int*   __restrict__ item_id,
                       const float* __restrict__ item_emb,
                       const float* __restrict__ aw1,
                       const float* __restrict__ aw2,
                       const float* __restrict__ ab2,
                       const float* __restrict__ afw,
                       const float* __restrict__ afb)
{
    extern __shared__ char smem[];
    uint32_t* b1P = (uint32_t*)(smem + OFF_B1);
    uint32_t* b2P = (uint32_t*)(smem + OFF_B2);
    float* tS     = (float*)(smem + OFF_T);
    float* cvec   = (float*)(smem + OFF_CVEC);
    float* ab2S   = (float*)(smem + OFF_AB2);
    float* afwS   = (float*)(smem + OFF_AFW);
    float* redS   = (float*)(smem + OFF_RED);

    const int tid = threadIdx.x, wid = tid >> 5, lid = tid & 31;
    const int b = blockIdx.x;
    const int g  = lid >> 2;
    const int tg = lid & 3;

    if (tid < 128) {
        long id = (long)item_id[b];
        tS[tid]   = item_emb[id * 128 + tid];
        cvec[tid] = g_cvec[b * 128 + tid];
    }
    if (tid < 64) { ab2S[tid] = __ldg(&ab2[tid]); afwS[tid] = __ldg(&afw[tid]); }
    __syncthreads();

    gather_chunk<128>(smem, OFF_SA0, in_item_id + b * LL, item_emb, tid);

    for (int e = tid; e < 128 * 64; e += 256) {
        int j = e & 127, kp = e >> 7;
        int k0 = kp * 2, k1 = k0 + 1;
        float v0 = tS[k0] * __ldg(&aw1[(128 + k0) * 128 + j]) - __ldg(&aw1[(256 + k0) * 128 + j]);
        float v1 = tS[k1] * __ldg(&aw1[(128 + k1) * 128 + j]) - __ldg(&aw1[(256 + k1) * 128 + j]);
        b1P[pidx(j, kp)] = pack2h(v0, v1);
    }
    for (int e = tid; e < 64 * 64; e += 256) {
        int n = e & 63, kp = e >> 6;
        float v0 = __ldg(&aw2[(kp * 2) * 64 + n]);
        float v1 = __ldg(&aw2[(kp * 2 + 1) * 64 + n]);
        b2P[pidx(n, kp)] = pack2h(v0, v1);
    }
    const float afb0 = __ldg(&afb[0]);
    __syncthreads();

    gather_chunk<72>(smem, OFF_SA1, in_item_id + b * LL + 128, item_emb, tid);

    const int rA   = wid * 16 + g;
    const int dAt  = tid & 127;
    const int half = tid >> 7;
    float attnReg = 0.0f;

    compute_chunk<128>(smem, OFF_SA0, in_item_id + b * LL,
                       afb0, attnReg, tid, wid, g, tg, rA, dAt, half);
    compute_chunk<72>(smem, OFF_SA1, in_item_id + b * LL + 128,
                      afb0, attnReg, tid, wid, g, tg, rA, dAt, half);

    if (tid >= 128) redS[dAt] = attnReg;
    __syncthreads();
    if (tid < 128) g_attn[b * 128 + tid] = attnReg + redS[tid];
}

// ============================================================================
// Fused MLP tail: fp32 end-to-end (precision-critical), k-quad float4 weight
// loads (bit-exact values, identical FMA order, 4x fewer LDG instructions).
// ============================================================================
#define NB 4
#define TM_ATTN 0
#define TM_T    (NB*128)
#define TM_CAT  (2*NB*128)
#define TM_H1   (TM_CAT + NB*384)
#define TM_H2   (TM_H1 + NB*512)
#define TM_H3   (TM_H2 + NB*256)
#define TM_TOT  (TM_H3 + NB*128)   // 24576 B

__global__ __launch_bounds__(256, 4)
void mlp_tail_kernel(const int*   __restrict__ item_id,
                     const float* __restrict__ item_emb,
                     const float* __restrict__ nb,
                     const float* __restrict__ db1,
                     const float* __restrict__ db2,
                     const float* __restrict__ db3,
                     const float* __restrict__ fw,
                     const float* __restrict__ fb,
                     const float* __restrict__ item_bias_tab,
                     float*       __restrict__ out)
{
    extern __shared__ float sm[];
    const int b0  = blockIdx.x * NB;
    const int tid = threadIdx.x;

    for (int e = tid; e < NB * 128; e += 256) {
        int bb = e >> 7, j = e & 127;
        sm[TM_ATTN + e] = g_attn[(b0 + bb) * 128 + j];
        long id = (long)__ldg(&item_id[b0 + bb]);
        sm[TM_T + e]    = __ldg(&item_emb[id * 128 + j]);
    }
    __syncthreads();

    // Phase A: attn2 = attn @ nw + nb ; build cat   (nw fp32 k-quad)
    {
        const int j = tid & 127;
        const int rbase = (tid >> 7) * 2;
        float acc[2];
        float nbj = __ldg(&nb[j]);
        acc[0] = nbj; acc[1] = nbj;
        #pragma unroll 4
        for (int k = 0; k < 128; k += 4) {
            float4 w = g_nwq[(k >> 2) * 128 + j];
            #pragma unroll
            for (int i = 0; i < 2; ++i) {
                float4 a = *reinterpret_cast<const float4*>(sm + TM_ATTN + (rbase + i) * 128 + k);
                acc[i] += a.x * w.x + a.y * w.y + a.z * w.z + a.w * w.w;
            }
        }
        #pragma unroll
        for (int i = 0; i < 2; ++i) {
            int r = rbase + i;
            float a2 = acc[i];
            float t  = sm[TM_T + r * 128 + j];
            sm[TM_CAT + r * 384 + j]       = a2;
            sm[TM_CAT + r * 384 + 128 + j] = t;
            sm[TM_CAT + r * 384 + 256 + j] = t * a2;
        }
    }
    __syncthreads();

    // Phase B: g1 = sigmoid(cat @ dw1 + db1)  384 -> 512   (dw1 fp32 k-quad)
    {
        const int j = tid;
        float acc0[NB], acc1[NB];
        float bj0 = __ldg(&db1[j]), bj1 = __ldg(&db1[j + 256]);
        #pragma unroll
        for (int r = 0; r < NB; ++r) { acc0[r] = bj0; acc1[r] = bj1; }
        #pragma unroll 4
        for (int k = 0; k < 384; k += 4) {
            float4 wa = g_dw1q[(k >> 2) * 512 + j];
            float4 wb = g_dw1q[(k >> 2) * 512 + j + 256];
            #pragma unroll
            for (int r = 0; r < NB; ++r) {
                float4 a = *reinterpret_cast<const float4*>(sm + TM_CAT + r * 384 + k);
                acc0[r] += a.x * wa.x + a.y * wa.y + a.z * wa.z + a.w * wa.w;
                acc1[r] += a.x * wb.x + a.y * wb.y + a.z * wb.z + a.w * wb.w;
            }
        }
        #pragma unroll
        for (int r = 0; r < NB; ++r) {
            sm[TM_H1 + r * 512 + j]       = sigm(acc0[r]);
            sm[TM_H1 + r * 512 + j + 256] = sigm(acc1[r]);
        }
    }
    __syncthreads();

    // Phase C: g2 = sigmoid(g1 @ dw2 + db2)  512 -> 256   (dw2 fp32 k-quad)
    {
        const int j = tid;
        float acc[NB];
        float bj = __ldg(&db2[j]);
        #pragma unroll
        for (int r = 0; r < NB; ++r) acc[r] = bj;
        #pragma unroll 4
        for (int k = 0; k < 512; k += 4) {
            float4 w = g_dw2q[(k >> 2) * 256 + j];
            #pragma unroll
            for (int r = 0; r < NB; ++r) {
                float4 a = *reinterpret_cast<const float4*>(sm + TM_H1 + r * 512 + k);
                acc[r] += a.x * w.x + a.y * w.y + a.z * w.z + a.w * w.w;
            }
        }
        #pragma unroll
        for (int r = 0; r < NB; ++r)
            sm[TM_H2 + r * 256 + j] = sigm(acc[r]);
    }
    __syncthreads();

    // Phase D: g3 = sigmoid(g2 @ dw3 + db3)  256 -> 128   (dw3 fp32 k-quad)
    {
        const int j = tid & 127;
        const int rbase = (tid >> 7) * 2;
        float acc[2];
        float bj = __ldg(&db3[j]);
        acc[0] = bj; acc[1] = bj;
        #pragma unroll 4
        for (int k = 0; k < 256; k += 4) {
            float4 w = g_dw3q[(k >> 2) * 128 + j];
            #pragma unroll
            for (int i = 0; i < 2; ++i) {
                float4 a = *reinterpret_cast<const float4*>(sm + TM_H2 + (rbase + i) * 256 + k);
                acc[i] += a.x * w.x + a.y * w.y + a.z * w.z + a.w * w.w;
            }
        }
        #pragma unroll
        for (int i = 0; i < 2; ++i)
            sm[TM_H3 + (rbase + i) * 128 + j] = sigm(acc[i]);
    }
    __syncthreads();

    // Phase E
    {
        const int wid  = tid >> 5;
        const int lane = tid & 31;
        if (wid < NB) {
            float v = 0.0f;
            #pragma unroll
            for (int q = 0; q < 4; ++q)
                v += sm[TM_H3 + wid * 128 + lane + 32 * q] * __ldg(&fw[lane + 32 * q]);
            #pragma unroll
            for (int m = 16; m > 0; m >>= 1) v += __shfl_xor_sync(0xffffffffu, v, m);
            if (lane == 0) {
                int b = b0 + wid;
                out[b] = v + __ldg(&fb[0]) + __ldg(&item_bias_tab[item_id[b]]);
            }
        }
    }
}

// ============================================================================
extern "C" void kernel_launch(void* const* d_in, const int* in_sizes, int n_in,
                              void* d_out, int out_size)
{
    const int*   in_item_id    = (const int*)  d_in[0];
    const int*   item_id       = (const int*)  d_in[1];
    const float* item_emb      = (const float*)d_in[2];
    const float* item_bias_tab = (const float*)d_in[3];
    const float* aw1 = (const float*)d_in[4];
    const float* ab1 = (const float*)d_in[5];
    const float* aw2 = (const float*)d_in[6];
    const float* ab2 = (const float*)d_in[7];
    const float* afw = (const float*)d_in[8];
    const float* afb = (const float*)d_in[9];
    const float* nw  = (const float*)d_in[10];
    const float* nb  = (const float*)d_in[11];
    const float* dw1 = (const float*)d_in[12];
    const float* db1 = (const float*)d_in[13];
    const float* dw2 = (const float*)d_in[14];
    const float* db2 = (const float*)d_in[15];
    const float* dw3 = (const float*)d_in[16];
    const float* db3 = (const float*)d_in[17];
    const float* fw  = (const float*)d_in[18];
    const float* fb  = (const float*)d_in[19];
    float* out = (float*)d_out;

    cudaFuncSetAttribute(din_attention_mma,
                         cudaFuncAttributeMaxDynamicSharedMemorySize, SMEM_BYTES);
    cudaFuncSetAttribute(mlp_tail_kernel,
                         cudaFuncAttributeMaxDynamicSharedMemorySize,
                         (int)(TM_TOT * sizeof(float)));

    prep_weights<<<128, 512>>>(nw, dw1, dw2, dw3);
    cvec_kernel<<<BB / 8, 512>>>(item_id, item_emb, aw1, ab1);
    din_attention_mma<<<BB, 256, SMEM_BYTES>>>(in_item_id, item_id, item_emb,
                                               aw1, aw2, ab2, afw, afb);
    mlp_tail_kernel<<<BB / NB, 256, TM_TOT * sizeof(float)>>>(
        item_id, item_emb, nb, db1, db2, db3, fw, fb, item_bias_tab, out);
}